// round 14
// speedup vs baseline: 7.0403x; 1.0141x over previous
#include <cuda_runtime.h>
#include <cuda_fp16.h>
#include <math.h>
#include <cstdint>
#include <type_traits>

// ---------------- problem constants ----------------
#define BATCH 32
#define ZL 64
#define SL 256
#define TT 320
#define NN 384
#define DIM 768
#define HEADS 12
#define HD 64
#define HID 3072
#define QKV3 2304

#define O_XOUT   0LL
#define O_GIT    7864320LL
#define O_GIS    7866368LL
#define O_ATTN   7874560LL
#define O_XIOUT  64497664LL
#define O_GITI   72361984LL
#define O_GISI   72364032LL
#define O_IATTN  72372224LL
#define O_ALPHA  128995328LL
#define O_UM     129003520LL
#define O_U      129011712LL
#define O_UI     129019904LL

#define SIDE_OUT 64497664LL
#define NND  (BATCH*NN*DIM)
#define TTD  (BATCH*TT*DIM)
#define TTH  (BATCH*TT*HID)
#define NNQ  (BATCH*NN*QKV3)
#define SLD  (BATCH*SL*DIM)

// ---------------- scratch ----------------
__device__ __half g_cath [BATCH*ZL*2*DIM];
__device__ __half g_zfh  [BATCH*ZL*DIM];
__device__ __half g_nsh  [SLD];
__device__ __half g_nsih [SLD];
__device__ float  g_attnx [BATCH*ZL*SL];
__device__ float  g_attnxi[BATCH*ZL*SL];
__device__ __half g_lnh2 [2*NND];
__device__ __half g_qkvh2[2*NNQ];
__device__ __half g_aoh2 [2*NND];
__device__ float  g_xattn2[2*NND];
__device__ __half g_vh   [SLD];
__device__ float  g_vf   [SLD];
__device__ float  g_xnew2[2*TTD];
__device__ __half g_lnvh [TTD];
__device__ __half g_lnx2 [2*TTD];
__device__ float  g_adap2[TTD];
__device__ __half g_hh2  [2*TTH];
__device__ __half g_wqkvh[QKV3*DIM];
__device__ __half g_wprojh[DIM*DIM];
__device__ __half g_wfc1h[HID*DIM];
__device__ __half g_wfc2h[DIM*HID];
__device__ __half g_walh [DIM*2*DIM];
__device__ __half g_wal2h[DIM*DIM];
__device__ __half g_wfush[DIM*DIM];

// =============== helpers =====================================================
__device__ __forceinline__ uint32_t smem_u32(const void* p) {
    uint32_t a;
    asm("{ .reg .u64 t; cvta.to.shared.u64 t, %1; cvt.u32.u64 %0, t; }" : "=r"(a) : "l"(p));
    return a;
}
__device__ __forceinline__ void mma16816h(float* d, const uint32_t* a, const uint32_t* b) {
    asm volatile("mma.sync.aligned.m16n8k16.row.col.f32.f16.f16.f32 "
        "{%0,%1,%2,%3}, {%4,%5,%6,%7}, {%8,%9}, {%0,%1,%2,%3};"
        : "+f"(d[0]), "+f"(d[1]), "+f"(d[2]), "+f"(d[3])
        : "r"(a[0]), "r"(a[1]), "r"(a[2]), "r"(a[3]), "r"(b[0]), "r"(b[1]));
}
__device__ __forceinline__ void ldsm4(uint32_t& r0, uint32_t& r1, uint32_t& r2, uint32_t& r3,
                                      uint32_t addr) {
    asm volatile("ldmatrix.sync.aligned.m8n8.x4.shared.b16 {%0,%1,%2,%3}, [%4];"
        : "=r"(r0), "=r"(r1), "=r"(r2), "=r"(r3) : "r"(addr));
}
__device__ __forceinline__ void ldsm4t(uint32_t& r0, uint32_t& r1, uint32_t& r2, uint32_t& r3,
                                       uint32_t addr) {
    asm volatile("ldmatrix.sync.aligned.m8n8.x4.trans.shared.b16 {%0,%1,%2,%3}, [%4];"
        : "=r"(r0), "=r"(r1), "=r"(r2), "=r"(r3) : "r"(addr));
}
__device__ __forceinline__ uint32_t pack_h2(float x, float y) {
    __half2 p = __float22half2_rn(make_float2(x, y));
    return *(uint32_t*)&p;
}
template<typename T> struct RawVec;
template<> struct RawVec<float>  { using type = float4; };
template<> struct RawVec<__half> { using type = uint2;  };
__device__ __forceinline__ uint2 to_h2(const float4& v) {
    return make_uint2(pack_h2(v.x, v.y), pack_h2(v.z, v.w));
}
__device__ __forceinline__ uint2 to_h2(const uint2& v) { return v; }
__device__ __forceinline__ void st_s(float* p, float v)  { *p = v; }
__device__ __forceinline__ void st_s(__half* p, float v) { *p = __float2half_rn(v); }
__device__ __forceinline__ void st2(float* p, float x, float y) {
    *(float2*)p = make_float2(x, y);
}
__device__ __forceinline__ void st2(__half* p, float x, float y) {
    *(uint32_t*)p = pack_h2(x, y);
}
__device__ __forceinline__ float wred(float v) {
    v += __shfl_xor_sync(0xFFFFFFFFu, v, 16);
    v += __shfl_xor_sync(0xFFFFFFFFu, v, 8);
    v += __shfl_xor_sync(0xFFFFFFFFu, v, 4);
    v += __shfl_xor_sync(0xFFFFFFFFu, v, 2);
    v += __shfl_xor_sync(0xFFFFFFFFu, v, 1);
    return v;
}

#define CP_ASYNC16(dst, src) \
    asm volatile("cp.async.cg.shared.global [%0], [%1], 16;" :: "r"(dst), "l"(src))
#define CP_COMMIT()  asm volatile("cp.async.commit_group;")
#define CP_WAIT0()   asm volatile("cp.async.wait_group 0;")

// =============== fp16 mma.sync GEMM, typed A/B/C =============================
#define RWH 40
#define RWA 72

template<int TM, int TN, typename TA, typename TB, typename TC>
__global__ __launch_bounds__(512, 2)
void mm2(const TA* __restrict__ A, const TB* __restrict__ B,
         const float* __restrict__ bias,
         const float* __restrict__ res1, const float* __restrict__ res2,
         TC* __restrict__ C,
         int K, int lda, int ldb, int ldc,
         long long sAb, long long sBb, long long sCb, int batchH,
         long long sAh, long long sBh, long long sCh,
         long long sR1b, long long sR2b,
         float alpha, int act)
{
    extern __shared__ char dsm[];
    constexpr int WTM = TM/4, WTN = TN/4;
    constexpr int MI = WTM/16, NI = WTN/8;
    constexpr bool ASYNC =
        std::is_same<TA,__half>::value && std::is_same<TB,__half>::value;

    const int tid  = threadIdx.x;
    const int lane = tid & 31;
    const int w    = tid >> 5;
    const int wm   = w >> 2;
    const int wn   = w & 3;

    const int bz = blockIdx.z;
    const int b  = bz / batchH;
    const int h  = bz - b*batchH;
    const int m0 = blockIdx.y * TM;
    const int n0 = blockIdx.x * TN;
    const TA* Ab = A + (long long)b*sAb + (long long)h*sAh + (long long)m0*lda;
    const TB* Bb = B + (long long)b*sBb + (long long)h*sBh + (long long)n0*ldb;
    const long long coffC  = (long long)b*sCb + (long long)h*sCh;
    const long long coffR1 = (long long)b*sR1b;
    const long long coffR2 = (long long)b*sR2b;

    const uint32_t sb0 = smem_u32(dsm);

    float acc[MI][NI][4];
    #pragma unroll
    for (int mi = 0; mi < MI; mi++)
        #pragma unroll
        for (int ni = 0; ni < NI; ni++)
            #pragma unroll
            for (int j = 0; j < 4; j++) acc[mi][ni][j] = 0.f;

    if constexpr (ASYNC) {
        constexpr int AHL = TM*RWA;
        constexpr int STAGE_BYTES = (TM + TN)*RWA*2;
        constexpr int PLA = TM*8/512, PLB = TN*8/512;
        const uint32_t a_l = (uint32_t)(((wm*WTM + (lane & 15))*RWA + ((lane >> 4) << 3)) * 2);
        const uint32_t b_l = (uint32_t)(AHL*2 + ((wn*WTN + (lane & 15))*RWA + ((lane >> 4) << 3)) * 2);
        const __half* Abh = (const __half*)Ab;
        const __half* Bbh = (const __half*)Bb;
        const int NC = K >> 6;

        #pragma unroll
        for (int p = 0; p < PLA; p++) {
            int u = tid + (p << 9);
            int r = u >> 3, ch = u & 7;
            CP_ASYNC16(sb0 + (uint32_t)(r*RWA*2 + ch*16),
                       Abh + (long long)r*lda + ch*8);
        }
        #pragma unroll
        for (int p = 0; p < PLB; p++) {
            int u = tid + (p << 9);
            int r = u >> 3, ch = u & 7;
            CP_ASYNC16(sb0 + (uint32_t)(AHL*2 + r*RWA*2 + ch*16),
                       Bbh + (long long)r*ldb + ch*8);
        }
        CP_COMMIT();

        for (int c = 0; c < NC; c++) {
            CP_WAIT0();
            __syncthreads();
            if (c + 1 < NC) {
                const int k0 = (c + 1) << 6;
                const uint32_t base = sb0 + ((c + 1) & 1) * STAGE_BYTES;
                #pragma unroll
                for (int p = 0; p < PLA; p++) {
                    int u = tid + (p << 9);
                    int r = u >> 3, ch = u & 7;
                    CP_ASYNC16(base + (uint32_t)(r*RWA*2 + ch*16),
                               Abh + (long long)r*lda + k0 + ch*8);
                }
                #pragma unroll
                for (int p = 0; p < PLB; p++) {
                    int u = tid + (p << 9);
                    int r = u >> 3, ch = u & 7;
                    CP_ASYNC16(base + (uint32_t)(AHL*2 + r*RWA*2 + ch*16),
                               Bbh + (long long)r*ldb + k0 + ch*8);
                }
                CP_COMMIT();
            }
            const uint32_t stageu = sb0 + (c & 1) * STAGE_BYTES;
            #pragma unroll
            for (int ks = 0; ks < 4; ks++) {
                const uint32_t kb = ks * 32;
                uint32_t ah[MI][4];
                #pragma unroll
                for (int mi = 0; mi < MI; mi++) {
                    uint32_t ad = stageu + a_l + mi*(16*RWA*2) + kb;
                    ldsm4(ah[mi][0], ah[mi][1], ah[mi][2], ah[mi][3], ad);
                }
                uint32_t bh[NI][2];
                #pragma unroll
                for (int nj = 0; nj < NI/2; nj++) {
                    uint32_t bd = stageu + b_l + nj*(16*RWA*2) + kb;
                    uint32_t q0, q1, q2, q3;
                    ldsm4(q0, q1, q2, q3, bd);
                    bh[2*nj][0] = q0; bh[2*nj][1] = q2;
                    bh[2*nj+1][0] = q1; bh[2*nj+1][1] = q3;
                }
                #pragma unroll
                for (int mi = 0; mi < MI; mi++)
                    #pragma unroll
                    for (int ni = 0; ni < NI; ni++)
                        mma16816h(acc[mi][ni], ah[mi], bh[ni]);
            }
        }
    } else {
        constexpr int AHL = TM*RWH;
        constexpr int STAGE_BYTES = (TM + TN)*RWH*2;
        constexpr int PA = TM/64, PB = TN/64;
        const uint32_t a_l = (uint32_t)(((wm*WTM + (lane & 15))*RWH + ((lane >> 4) << 3)) * 2);
        const uint32_t b_l = (uint32_t)(AHL*2 + ((wn*WTN + (lane & 15))*RWH + ((lane >> 4) << 3)) * 2);
        const int lq = tid & 7;
        const int lr = tid >> 3;
        const int NC = K >> 5;
        typename RawVec<TA>::type pA[PA];
        typename RawVec<TB>::type pB[PB];

        #pragma unroll
        for (int p = 0; p < PA; p++)
            pA[p] = *(const typename RawVec<TA>::type*)(Ab + (long long)(lr + 64*p)*lda + 4*lq);
        #pragma unroll
        for (int p = 0; p < PB; p++)
            pB[p] = *(const typename RawVec<TB>::type*)(Bb + (long long)(lr + 64*p)*ldb + 4*lq);

        for (int c = 0; c < NC; c++) {
            const int st = c & 1;
            char* sb = dsm + st * STAGE_BYTES;
            __half* Ah = (__half*)sb;
            __half* Bh = Ah + AHL;

            #pragma unroll
            for (int p = 0; p < PA; p++)
                *(uint2*)(Ah + (lr + 64*p)*RWH + 4*lq) = to_h2(pA[p]);
            #pragma unroll
            for (int p = 0; p < PB; p++)
                *(uint2*)(Bh + (lr + 64*p)*RWH + 4*lq) = to_h2(pB[p]);
            __syncthreads();

            if (c + 1 < NC) {
                const int k0 = (c + 1) << 5;
                #pragma unroll
                for (int p = 0; p < PA; p++)
                    pA[p] = *(const typename RawVec<TA>::type*)(Ab + (long long)(lr + 64*p)*lda + k0 + 4*lq);
                #pragma unroll
                for (int p = 0; p < PB; p++)
                    pB[p] = *(const typename RawVec<TB>::type*)(Bb + (long long)(lr + 64*p)*ldb + k0 + 4*lq);
            }

            const uint32_t stageu = sb0 + st * STAGE_BYTES;
            #pragma unroll
            for (int ks = 0; ks < 2; ks++) {
                const uint32_t kb = ks * 32;
                uint32_t ah[MI][4];
                #pragma unroll
                for (int mi = 0; mi < MI; mi++) {
                    uint32_t ad = stageu + a_l + mi*(16*RWH*2) + kb;
                    ldsm4(ah[mi][0], ah[mi][1], ah[mi][2], ah[mi][3], ad);
                }
                uint32_t bh[NI][2];
                #pragma unroll
                for (int nj = 0; nj < NI/2; nj++) {
                    uint32_t bd = stageu + b_l + nj*(16*RWH*2) + kb;
                    uint32_t q0, q1, q2, q3;
                    ldsm4(q0, q1, q2, q3, bd);
                    bh[2*nj][0] = q0; bh[2*nj][1] = q2;
                    bh[2*nj+1][0] = q1; bh[2*nj+1][1] = q3;
                }
                #pragma unroll
                for (int mi = 0; mi < MI; mi++)
                    #pragma unroll
                    for (int ni = 0; ni < NI; ni++)
                        mma16816h(acc[mi][ni], ah[mi], bh[ni]);
            }
            __syncthreads();
        }
    }

    // ---- epilogue: direct fragment stores ----
    const int g = lane >> 2, t4 = lane & 3;
    float2 bv[NI];
    if (bias) {
        #pragma unroll
        for (int ni = 0; ni < NI; ni++)
            bv[ni] = *(const float2*)(bias + n0 + wn*WTN + ni*8 + 2*t4);
    }
    #pragma unroll
    for (int mi = 0; mi < MI; mi++)
        #pragma unroll
        for (int h2 = 0; h2 < 2; h2++) {
            long long row = m0 + wm*WTM + mi*16 + g + 8*h2;
            long long base = row*(long long)ldc + n0 + wn*WTN + 2*t4;
            #pragma unroll
            for (int ni = 0; ni < NI; ni++) {
                float vx = acc[mi][ni][2*h2]   * alpha;
                float vy = acc[mi][ni][2*h2+1] * alpha;
                if (bias) { vx += bv[ni].x; vy += bv[ni].y; }
                long long off = base + ni*8;
                if (res1) { float2 a = *(const float2*)(res1 + coffR1 + off); vx += a.x; vy += a.y; }
                if (res2) { float2 a = *(const float2*)(res2 + coffR2 + off); vx += a.x; vy += a.y; }
                if (act == 1) {
                    vx = 0.5f*vx*(1.f + erff(vx*0.70710678118654752f));
                    vy = 0.5f*vy*(1.f + erff(vy*0.70710678118654752f));
                }
                st2(C + coffC + off, vx, vy);
            }
        }
}

// =============== fused QK^T + softmax + P@V, dual-stream, direct V ===========
#define RW2 72
#define RW3 392
#define RWV 72
#define PV_SMEM (128*RW3*2 + 384*RWV*2 + 128*4*4 + 128*4)

__global__ __launch_bounds__(512, 1)
void attn_fused(const __half* __restrict__ qkv2,
                float* __restrict__ attn_base, __half* __restrict__ ao2)
{
    extern __shared__ char dsm[];
    __half* Ph  = (__half*)dsm;
    __half* Vs  = (__half*)(dsm + 128*RW3*2);
    float*  red = (float*)(dsm + 128*RW3*2 + 384*RWV*2);
    float*  invb= red + 128*4;
    __half* Qs  = (__half*)dsm;
    __half* Ks  = Qs + 128*RW2;

    const int tid = threadIdx.x;
    const int lane = tid & 31;
    const int w = tid >> 5;
    const int wm = w >> 2, wn = w & 3;
    const int g = lane >> 2, t4 = lane & 3;

    const int m0 = blockIdx.x * 128;
    const int sy = blockIdx.y;
    const int side = sy / (BATCH*HEADS);
    const int bh = sy - side*(BATCH*HEADS);
    const int b  = bh / HEADS;
    const int hh = bh - b*HEADS;

    const __half* qkv = qkv2 + (long long)side*NNQ;
    float* attn = attn_base + (long long)side*SIDE_OUT;
    __half* ao  = ao2 + (long long)side*NND;

    const __half* qbase = qkv + (long long)b*NN*QKV3 + hh*HD;

    #pragma unroll
    for (int p = 0; p < 2; p++) {
        int u = tid + (p << 9);
        int r = u >> 3, ch = u & 7;
        *(uint4*)(Qs + r*RW2 + ch*8) =
            *(const uint4*)(qbase + (long long)(m0 + r)*QKV3 + ch*8);
    }
    #pragma unroll
    for (int p = 0; p < 6; p++) {
        int u = tid + (p << 9);
        int r = u >> 3, ch = u & 7;
        *(uint4*)(Ks + r*RW2 + ch*8) =
            *(const uint4*)(qbase + DIM + (long long)r*QKV3 + ch*8);
    }
    #pragma unroll
    for (int p = 0; p < 6; p++) {
        int u = tid + (p << 9);
        int r = u >> 3, ch = u & 7;
        *(uint4*)(Vs + r*RWV + ch*8) =
            *(const uint4*)(qbase + 2*DIM + (long long)r*QKV3 + ch*8);
    }
    __syncthreads();

    const uint32_t sq = smem_u32(Qs);
    const uint32_t sk = smem_u32(Ks);
    const uint32_t a_l = sq + ((wm*32 + (lane & 15))*RW2 + ((lane >> 4) << 3)) * 2;
    const uint32_t b_l = sk + ((wn*96 + (lane & 15))*RW2 + ((lane >> 4) << 3)) * 2;

    float acc[2][12][4];
    #pragma unroll
    for (int mi = 0; mi < 2; mi++)
        #pragma unroll
        for (int ni = 0; ni < 12; ni++)
            #pragma unroll
            for (int j = 0; j < 4; j++) acc[mi][ni][j] = 0.f;

    #pragma unroll
    for (int ks = 0; ks < 4; ks++) {
        const uint32_t kb = ks * 32;
        uint32_t ah[2][4];
        #pragma unroll
        for (int mi = 0; mi < 2; mi++)
            ldsm4(ah[mi][0], ah[mi][1], ah[mi][2], ah[mi][3],
                  a_l + mi*(16*RW2*2) + kb);
        #pragma unroll
        for (int nj = 0; nj < 6; nj++) {
            uint32_t q0, q1, q2, q3;
            ldsm4(q0, q1, q2, q3, b_l + nj*(16*RW2*2) + kb);
            uint32_t b0[2] = {q0, q2}, b1[2] = {q1, q3};
            #pragma unroll
            for (int mi = 0; mi < 2; mi++) {
                mma16816h(acc[mi][2*nj],   ah[mi], b0);
                mma16816h(acc[mi][2*nj+1], ah[mi], b1);
            }
        }
    }

    #pragma unroll
    for (int mi = 0; mi < 2; mi++)
        #pragma unroll
        for (int ni = 0; ni < 12; ni++)
            #pragma unroll
            for (int j = 0; j < 4; j++) acc[mi][ni][j] *= 0.125f;

    float M[2][2];
    #pragma unroll
    for (int mi = 0; mi < 2; mi++)
        #pragma unroll
        for (int h2 = 0; h2 < 2; h2++) {
            float m = -1e30f;
            #pragma unroll
            for (int ni = 0; ni < 12; ni++)
                m = fmaxf(m, fmaxf(acc[mi][ni][2*h2], acc[mi][ni][2*h2+1]));
            m = fmaxf(m, __shfl_xor_sync(0xFFFFFFFFu, m, 1));
            m = fmaxf(m, __shfl_xor_sync(0xFFFFFFFFu, m, 2));
            if (t4 == 0) red[(wm*32 + mi*16 + g + 8*h2)*4 + wn] = m;
        }
    __syncthreads();
    #pragma unroll
    for (int mi = 0; mi < 2; mi++)
        #pragma unroll
        for (int h2 = 0; h2 < 2; h2++) {
            int row = wm*32 + mi*16 + g + 8*h2;
            M[mi][h2] = fmaxf(fmaxf(red[row*4], red[row*4+1]),
                              fmaxf(red[row*4+2], red[row*4+3]));
        }
    __syncthreads();

    float S[2][2];
    #pragma unroll
    for (int mi = 0; mi < 2; mi++)
        #pragma unroll
        for (int h2 = 0; h2 < 2; h2++) {
            float s = 0.f;
            #pragma unroll
            for (int ni = 0; ni < 12; ni++) {
                float e0 = __expf(acc[mi][ni][2*h2]   - M[mi][h2]);
                float e1 = __expf(acc[mi][ni][2*h2+1] - M[mi][h2]);
                acc[mi][ni][2*h2] = e0; acc[mi][ni][2*h2+1] = e1;
                s += e0 + e1;
            }
            s += __shfl_xor_sync(0xFFFFFFFFu, s, 1);
            s += __shfl_xor_sync(0xFFFFFFFFu, s, 2);
            if (t4 == 0) red[(wm*32 + mi*16 + g + 8*h2)*4 + wn] = s;
        }
    __syncthreads();
    #pragma unroll
    for (int mi = 0; mi < 2; mi++)
        #pragma unroll
        for (int h2 = 0; h2 < 2; h2++) {
            int row = wm*32 + mi*16 + g + 8*h2;
            float inv = 1.f / (red[row*4] + red[row*4+1] + red[row*4+2] + red[row*4+3]);
            S[mi][h2] = inv;
            if (wn == 0 && t4 == 0) invb[row] = inv;
        }

    float* abase = attn + (long long)bh*NN*NN;
    #pragma unroll
    for (int mi = 0; mi < 2; mi++)
        #pragma unroll
        for (int h2 = 0; h2 < 2; h2++) {
            int row = m0 + wm*32 + mi*16 + g + 8*h2;
            float inv = S[mi][h2];
            float* rp = abase + (long long)row*NN + wn*96 + 2*t4;
            #pragma unroll
            for (int ni = 0; ni < 12; ni++) {
                float2 o;
                o.x = acc[mi][ni][2*h2]   * inv;
                o.y = acc[mi][ni][2*h2+1] * inv;
                *(float2*)(rp + ni*8) = o;
            }
        }

    __syncthreads();

    #pragma unroll
    for (int mi = 0; mi < 2; mi++)
        #pragma unroll
        for (int h2 = 0; h2 < 2; h2++) {
            int row = wm*32 + mi*16 + g + 8*h2;
            __half* rp = Ph + row*RW3 + wn*96 + 2*t4;
            #pragma unroll
            for (int ni = 0; ni < 12; ni++)
                *(uint32_t*)(rp + ni*8) = pack_h2(acc[mi][ni][2*h2], acc[mi][ni][2*h2+1]);
        }
    __syncthreads();

    const int wm2 = w >> 2, wn2 = w & 3;
    const uint32_t pa = smem_u32(Ph) + ((wm2*32 + (lane & 15))*RW3 + ((lane >> 4) << 3))*2;
    const int grp = lane >> 3, rr8 = lane & 7;
    const uint32_t v_l = smem_u32(Vs) +
        (uint32_t)(((((grp & 1) * 8) + rr8)*RWV + ((grp >> 1) * 8) + wn2*16) * 2);

    float acc2[2][2][4];
    #pragma unroll
    for (int mi = 0; mi < 2; mi++)
        #pragma unroll
        for (int ni = 0; ni < 2; ni++)
            #pragma unroll
            for (int j = 0; j < 4; j++) acc2[mi][ni][j] = 0.f;

    #pragma unroll
    for (int ks = 0; ks < 24; ks++) {
        uint32_t ah0[4], ah1[4], q0, q1, q2, q3;
        ldsm4(ah0[0], ah0[1], ah0[2], ah0[3], pa + ks*32);
        ldsm4(ah1[0], ah1[1], ah1[2], ah1[3], pa + 16*RW3*2 + ks*32);
        ldsm4t(q0, q1, q2, q3, v_l + (uint32_t)(ks*16*RWV*2));
        uint32_t b0[2] = {q0, q1}, b1[2] = {q2, q3};
        mma16816h(acc2[0][0], ah0, b0);
        mma16816h(acc2[0][1], ah0, b1);
        mma16816h(acc2[1][0], ah1, b0);
        mma16816h(acc2[1][1], ah1, b1);
    }

    #pragma unroll
    for (int mi = 0; mi < 2; mi++) {
        int r0 = wm2*32 + mi*16 + g;
        float inv0 = invb[r0], inv1 = invb[r0 + 8];
        long long base0 = ((long long)b*NN + m0 + r0)*DIM + hh*HD;
        long long base1 = base0 + 8LL*DIM;
        #pragma unroll
        for (int ni = 0; ni < 2; ni++) {
            int col = wn2*16 + ni*8 + 2*t4;
            *(uint32_t*)(ao + base0 + col) = pack_h2(acc2[mi][ni][0]*inv0, acc2[mi][ni][1]*inv0);
            *(uint32_t*)(ao + base1 + col) = pack_h2(acc2[mi][ni][2]*inv1, acc2[mi][ni][3]*inv1);
        }
    }
}

// ---------------- LayerNorm over ns/nsi ----------------
__global__ void ln_ns_k(const float* __restrict__ x, const float* __restrict__ xi,
                        __half* __restrict__ nsh, __half* __restrict__ nsih,
                        const float* __restrict__ g, const float* __restrict__ b)
{
    int t = blockIdx.x, bb = blockIdx.y, side = blockIdx.z;
    const float* src = (side ? xi : x) + (long long)ZL*DIM + ((long long)bb*TT + t)*DIM;
    __half* y = (side ? nsih : nsh) + ((long long)bb*SL + t)*DIM;
    int tid = threadIdx.x;
    int wid = tid >> 5, lane = tid & 31;
    float v0 = src[tid], v1 = src[tid+256], v2 = src[tid+512];
    float s = wred(v0 + v1 + v2);
    float q = wred(v0*v0 + v1*v1 + v2*v2);
    __shared__ float ws[8], wq[8];
    if (lane == 0) { ws[wid] = s; wq[wid] = q; }
    __syncthreads();
    float S = 0.f, Q = 0.f;
    #pragma unroll
    for (int k = 0; k < 8; k++) { S += ws[k]; Q += wq[k]; }
    float mean = S * (1.f/768.f);
    float inv = rsqrtf(Q * (1.f/768.f) - mean*mean + 1e-5f);
    y[tid]     = __float2half_rn((v0-mean)*inv*g[tid]     + b[tid]);
    y[tid+256] = __float2half_rn((v1-mean)*inv*g[tid+256] + b[tid+256]);
    y[tid+512] = __float2half_rn((v2-mean)*inv*g[tid+512] + b[tid+512]);
}

// LN over concat [z_f(fp16), x/xi(fp32)]
__global__ void ln_cat_kernel(const __half* __restrict__ zf,
                              const float* __restrict__ x, const float* __restrict__ xi,
                              __half* __restrict__ out2,
                              const float* __restrict__ g, const float* __restrict__ b)
{
    int t = blockIdx.x, bb = blockIdx.y, side = blockIdx.z;
    const float* xs = side ? xi : x;
    __half* y = out2 + (long long)side*NND + ((long long)bb*NN + t)*DIM;
    int tid = threadIdx.x;
    int wid = tid >> 5, lane = tid & 31;
    float v0, v1, v2;
    if (t < ZL) {
        const __half* src = zf + ((long long)bb*ZL + t)*DIM;
        v0 = __half2float(src[tid]);
        v1 = __half2float(src[tid+256]);
        v2 = __half2float(src[tid+512]);
    } else {
        const float* src = xs + ((long long)bb*TT + (t - ZL))*DIM;
        v0 = src[tid]; v1 = src[tid+256]; v2 = src[tid+512];
    }
    float s = wred(v0 + v1 + v2);
    float q = wred(v0*v0 + v1*v1 + v2*v2);
    __shared__ float ws[8], wq[8];
    if (lane == 0) { ws[wid] = s; wq[wid] = q; }
    __syncthreads();
    float S = 0.f, Q = 0.f;
    #pragma unroll
    for (int k = 0; k < 8; k++) { S += ws[k]; Q += wq[k]; }
    float mean = S * (1.f/768.f);
    float inv = rsqrtf(Q * (1.f/768.f) - mean*mean + 1e-5f);
    y[tid]     = __float2half_rn((v0-mean)*inv*g[tid]     + b[tid]);
    y[tid+256] = __float2half_rn((v1-mean)*inv*g[tid+256] + b[tid+256]);
    y[tid+512] = __float2half_rn((v2-mean)*inv*g[tid+512] + b[tid+512]);
}

// ---------------- fused residual + 3x LayerNorm ------------------------------
__global__ void resid_ln_k(const float* __restrict__ x, const float* __restrict__ xi,
                           const float* __restrict__ xattn2,
                           const float* __restrict__ vfus,
                           const float* __restrict__ g2, const float* __restrict__ bt2,
                           float* __restrict__ xnew2,
                           __half* __restrict__ lnv, __half* __restrict__ lnx2)
{
    const int t = blockIdx.x, b = blockIdx.y;
    const int tid = threadIdx.x;
    const int wid = tid >> 5, lane = tid & 31;
    const long long rbase = ((long long)b*TT + t)*DIM;
    const long long abase = ((long long)b*NN + ZL + t)*DIM;
    const float* xattn  = xattn2;
    const float* xiattn = xattn2 + NND;
    const float* vsrc = (t < ZL) ? xiattn + ((long long)b*NN + t)*DIM
                                 : vfus   + ((long long)b*SL + (t - ZL))*DIM;

    float vf[3], xo[3], xio[3];
    float s[6] = {0,0,0,0,0,0};
    #pragma unroll
    for (int j = 0; j < 3; j++) {
        int c = tid + j*256;
        float vv = vsrc[c];
        float a1 = xattn[abase + c], a2 = xiattn[abase + c];
        float xv = x[rbase + c] + a1 + vv;
        float xiv = xi[rbase + c] + a2 + vv;
        vf[j] = vv; xo[j] = xv; xio[j] = xiv;
        xnew2[rbase + c]       = xv;
        xnew2[TTD + rbase + c] = xiv;
        s[0] += vv;  s[1] += vv*vv;
        s[2] += xv;  s[3] += xv*xv;
        s[4] += xiv; s[5] += xiv*xiv;
    }

    #pragma unroll
    for (int k = 0; k < 6; k++) s[k] = wred(s[k]);
    __shared__ float sh[6][8];
    if (lane == 0) {
        #pragma unroll
        for (int k = 0; k < 6; k++) sh[k][wid] = s[k];
    }
    __syncthreads();
    float tot[6];
    #pragma unroll
    for (int k = 0; k < 6; k++) {
        float acc = 0.f;
        #pragma unroll
        for (int p = 0; p < 8; p++) acc += sh[k][p];
        tot[k] = acc;
    }
    float mv = tot[0]*(1.f/768.f), iv = rsqrtf(tot[1]*(1.f/768.f) - mv*mv + 1e-5f);
    float mx = tot[2]*(1.f/768.f), ix = rsqrtf(tot[3]*(1.f/768.f) - mx*mx + 1e-5f);
    float mi2 = tot[4]*(1.f/768.f), ii = rsqrtf(tot[5]*(1.f/768.f) - mi2*mi2 + 1e-5f);

    #pragma unroll
    for (int j = 0; j < 3; j++) {
        int c = tid + j*256;
        float gg = g2[c], bb = bt2[c];
        lnv[rbase + c]        = __float2half_rn((vf[j]-mv)*iv*gg + bb);
        lnx2[rbase + c]       = __float2half_rn((xo[j]-mx)*ix*gg + bb);
        lnx2[TTD + rbase + c] = __float2half_rn((xio[j]-mi2)*ii*gg + bb);
    }
}

// ---------------- fusion ----------------
__global__ void fusion_kernel(const float* __restrict__ ax, const float* __restrict__ axi,
                              float* __restrict__ alpha_o, float* __restrict__ um_o,
                              float* __restrict__ u_o, float* __restrict__ ui_o)
{
    int b = blockIdx.x, s = threadIdx.x;
    const float* X  = ax  + (long long)b*ZL*SL + s;
    const float* Xi = axi + (long long)b*ZL*SL + s;
    float u, ui;
    {
        float mx = -1e30f;
        for (int t = 0; t < ZL; t++) mx = fmaxf(mx, X[t*SL]);
        float sum = 0.f;
        for (int t = 0; t < ZL; t++) sum += expf(X[t*SL] - mx);
        float inv = 1.f/sum, acc = 0.f;
        for (int t = 0; t < ZL; t++) { float p = expf(X[t*SL]-mx)*inv; acc -= p*logf(p + 1e-8f); }
        u = acc;
    }
    {
        float mx = -1e30f;
        for (int t = 0; t < ZL; t++) mx = fmaxf(mx, Xi[t*SL]);
        float sum = 0.f;
        for (int t = 0; t < ZL; t++) sum += expf(Xi[t*SL] - mx);
        float inv = 1.f/sum, acc = 0.f;
        for (int t = 0; t < ZL; t++) { float p = expf(Xi[t*SL]-mx)*inv; acc -= p*logf(p + 1e-8f); }
        ui = acc;
    }
    int idx = b*SL + s;
    float alpha = 1.f / (1.f + expf(-(ui - u)));
    alpha_o[idx] = alpha;
    um_o[idx] = 0.5f*(u + ui);
    u_o[idx] = u;
    ui_o[idx] = ui;
}

// ---------------- elementwise helpers ----------------
__global__ void cat_feat_k(const float* __restrict__ x, const float* __restrict__ xi,
                           __half* __restrict__ o)
{
    long long i = (long long)blockIdx.x*blockDim.x + threadIdx.x;
    const long long n = (long long)BATCH*ZL*2*DIM;
    if (i >= n) return;
    int c = (int)(i % (2*DIM));
    long long bt = i / (2*DIM);
    long long b = bt / ZL, t = bt % ZL;
    long long src = (b*TT + t)*DIM;
    float v = (c < DIM) ? x[src + c] : xi[src + c - DIM];
    o[i] = __float2half_rn(v);
}

__global__ void make_v_k(const __half* __restrict__ ns, const __half* __restrict__ nsi,
                         const float* __restrict__ alpha, __half* __restrict__ v)
{
    long long i = (long long)blockIdx.x*blockDim.x + threadIdx.x;
    const long long n = (long long)SLD;
    if (i >= n) return;
    long long bs = i / DIM;
    float a = alpha[bs];
    v[i] = __float2half_rn(a*__half2float(ns[i]) + (1.f - a)*__half2float(nsi[i]));
}

__global__ void i2f_all(const int* a0, float* o0, int n0,
                        const int* a1, float* o1, int n1,
                        const int* a2, float* o2, int n2,
                        const int* a3, float* o3, int n3)
{
    int i = blockIdx.x*blockDim.x + threadIdx.x;
    if      (i < n0)          o0[i] = (float)a0[i];
    else if ((i -= n0) < n1)  o1[i] = (float)a1[i];
    else if ((i -= n1) < n2)  o2[i] = (float)a2[i];
    else if ((i -= n2) < n3)  o3[i] = (float)a3[i];
}

// single-tensor f2h (w_al, needed early on main)
__global__ void f2h_one(const float* __restrict__ s, __half* __restrict__ d, int n4)
{
    int i = blockIdx.x*blockDim.x + threadIdx.x;
    if (i < n4) {
        float4 v = *(const float4*)(s + 4*i);
        *(uint2*)(d + 4*i) = to_h2(v);
    }
}

// remaining 6 weight conversions (runs on s2)
__global__ void f2h_rest(const float* s0, __half* d0, int n0,
                         const float* s1, __half* d1, int n1,
                         const float* s2, __half* d2, int n2,
                         const float* s3, __half* d3, int n3,
                         const float* s4, __half* d4, int n4,
                         const float* s5, __half* d5, int n5)
{
    int i = blockIdx.x*blockDim.x + threadIdx.x;
    const float* s; __half* d;
    if      (i < n0)                      { s = s0; d = d0; }
    else if ((i -= n0) < n1)              { s = s1; d = d1; }
    else if ((i -= n1) < n2)              { s = s2; d = d2; }
    else if ((i -= n2) < n3)              { s = s3; d = d3; }
    else if ((i -= n3) < n4)              { s = s4; d = d4; }
    else if ((i -= n4) < n5)              { s = s5; d = d5; }
    else return;
    float4 v = *(const float4*)(s + 4*i);
    *(uint2*)(d + 4*i) = to_h2(v);
}

// ---------------- host-side helpers ----------------
template<int TM, int TN, typename TA, typename TB, typename TC>
static inline void mm(cudaStream_t st,
                      const TA* A, const TB* B, const float* bias,
                      const float* r1, const float* r2, TC* C,
                      int M, int N, int K, int lda, int ldb, int ldc,
                      long long sAb, long long sBb, long long sCb,
                      int nb, int nh,
                      long long sAh, long long sBh, long long sCh,
                      long long sR1b, long long sR2b,
                      float alpha, int act)
{
    constexpr bool ASYNC =
        std::is_same<TA,__half>::value && std::is_same<TB,__half>::value;
    constexpr int DS = 2 * (ASYNC ? (TM + TN)*RWA*2 : (TM + TN)*RWH*2);
    static bool init = false;
    if (!init) {
        cudaFuncSetAttribute(mm2<TM,TN,TA,TB,TC>, cudaFuncAttributeMaxDynamicSharedMemorySize, DS);
        init = true;
    }
    dim3 g(N/TN, M/TM, nb*nh);
    mm2<TM,TN,TA,TB,TC><<<g, 512, DS, st>>>(A,B,bias,r1,r2,C,K,lda,ldb,ldc,
        sAb,sBb,sCb,nh,sAh,sBh,sCh,sR1b,sR2b,alpha,act);
}

static inline int cdiv(long long a, int b) { return (int)((a + b - 1) / b); }

extern "C" void kernel_launch(void* const* d_in, const int* in_sizes, int n_in,
                              void* d_out, int out_size)
{
    const float* x      = (const float*)d_in[0];
    const float* xi     = (const float*)d_in[1];
    const int*   git    = (const int*)  d_in[2];
    const int*   giti   = (const int*)  d_in[3];
    const int*   gis    = (const int*)  d_in[4];
    const int*   gisi   = (const int*)  d_in[5];
    const float* w_qkv  = (const float*)d_in[6];
    const float* b_qkv  = (const float*)d_in[7];
    const float* w_proj = (const float*)d_in[8];
    const float* b_proj = (const float*)d_in[9];
    const float* g1     = (const float*)d_in[10];
    const float* bt1    = (const float*)d_in[11];
    const float* g2     = (const float*)d_in[12];
    const float* bt2    = (const float*)d_in[13];
    const float* w_fc1  = (const float*)d_in[14];
    const float* b_fc1  = (const float*)d_in[15];
    const float* w_fc2  = (const float*)d_in[16];
    const float* b_fc2  = (const float*)d_in[17];
    const float* w_al   = (const float*)d_in[18];
    const float* b_al   = (const float*)d_in[19];
    const float* w_al2  = (const float*)d_in[20];
    const float* b_al2  = (const float*)d_in[21];
    const float* w_fus  = (const float*)d_in[22];
    const float* b_fus  = (const float*)d_in[23];
    float* out = (float*)d_out;

    float *p_attnx, *p_attnxi, *p_xattn2, *p_vf, *p_xnew2, *p_adap2;
    __half *p_cath, *p_zfh, *p_nsh, *p_nsih, *p_lnh2, *p_qkvh2, *p_aoh2,
           *p_hh2, *p_vh, *p_lnvh, *p_lnx2;
    __half *wqkvh, *wprojh, *wfc1h, *wfc2h, *walh, *wal2h, *wfush;
    cudaGetSymbolAddress((void**)&p_cath,   g_cath);
    cudaGetSymbolAddress((void**)&p_zfh,    g_zfh);
    cudaGetSymbolAddress((void**)&p_nsh,    g_nsh);
    cudaGetSymbolAddress((void**)&p_nsih,   g_nsih);
    cudaGetSymbolAddress((void**)&p_attnx,  g_attnx);
    cudaGetSymbolAddress((void**)&p_attnxi, g_attnxi);
    cudaGetSymbolAddress((void**)&p_lnh2,   g_lnh2);
    cudaGetSymbolAddress((void**)&p_qkvh2,  g_qkvh2);
    cudaGetSymbolAddress((void**)&p_aoh2,   g_aoh2);
    cudaGetSymbolAddress((void**)&p_xattn2, g_xattn2);
    cudaGetSymbolAddress((void**)&p_vh,     g_vh);
    cudaGetSymbolAddress((void**)&p_vf,     g_vf);
    cudaGetSymbolAddress((void**)&p_xnew2,  g_xnew2);
    cudaGetSymbolAddress((void**)&p_lnvh,   g_lnvh);
    cudaGetSymbolAddress((void**)&p_lnx2,   g_lnx2);
    cudaGetSymbolAddress((void**)&p_adap2,  g_adap2);
    cudaGetSymbolAddress((void**)&p_hh2,    g_hh2);
    cudaGetSymbolAddress((void**)&wqkvh,    g_wqkvh);
    cudaGetSymbolAddress((void**)&wprojh,   g_wprojh);
    cudaGetSymbolAddress((void**)&wfc1h,    g_wfc1h);
    cudaGetSymbolAddress((void**)&wfc2h,    g_wfc2h);
    cudaGetSymbolAddress((void**)&walh,     g_walh);
    cudaGetSymbolAddress((void**)&wal2h,    g_wal2h);
    cudaGetSymbolAddress((void**)&wfush,    g_wfush);

    static cudaStream_t s2 = nullptr;
    static cudaEvent_t evStart = nullptr, evW = nullptr, evZf = nullptr,
                       evJoin = nullptr, evResid = nullptr, evAdap = nullptr;
    if (!s2) {
        cudaStreamCreateWithFlags(&s2, cudaStreamNonBlocking);
        cudaEventCreateWithFlags(&evStart, cudaEventDisableTiming);
        cudaEventCreateWithFlags(&evW,     cudaEventDisableTiming);
        cudaEventCreateWithFlags(&evZf,    cudaEventDisableTiming);
        cudaEventCreateWithFlags(&evJoin,  cudaEventDisableTiming);
        cudaEventCreateWithFlags(&evResid, cudaEventDisableTiming);
        cudaEventCreateWithFlags(&evAdap,  cudaEventDisableTiming);
    }

    const float scale_dim = 1.f / sqrtf((float)DIM);

    // ======= fork s2 from the very start =======
    cudaEventRecord(evStart, 0);
    cudaStreamWaitEvent(s2, evStart, 0);

    // s2: big weight conversions + ns/nsi LN + index passthroughs
    {
        const int n0 = QKV3*DIM/4, n1 = DIM*DIM/4, n2 = HID*DIM/4, n3 = DIM*HID/4,
                  n5 = DIM*DIM/4, n6 = DIM*DIM/4;
        f2h_rest<<<cdiv(n0+n1+n2+n3+n5+n6, 256), 256, 0, s2>>>(
            w_qkv, wqkvh, n0,  w_proj, wprojh, n1,  w_fc1, wfc1h, n2,
            w_fc2, wfc2h, n3,  w_al2, wal2h, n5,  w_fus, wfush, n6);
    }
    cudaEventRecord(evW, s2);
    ln_ns_k<<<dim3(SL, BATCH, 2), 256, 0, s2>>>(x, xi, p_nsh, p_nsih, g1, bt1);
    i2f_all<<<cdiv(2*(BATCH*ZL + BATCH*SL), 256), 256, 0, s2>>>(
        git,  out + O_GIT,  BATCH*ZL,
        gis,  out + O_GIS,  BATCH*SL,
        giti, out + O_GITI, BATCH*ZL,
        gisi, out + O_GISI, BATCH*SL);

    // main: walh conversion + cat + zf GEMM
    f2h_one<<<cdiv(DIM*2*DIM/4, 256), 256>>>(w_al, walh, DIM*2*DIM/4);
    cat_feat_k<<<cdiv((long long)BATCH*ZL*2*DIM, 256), 256>>>(x, xi, p_cath);
    mm<128,128,__half,__half,__half>(0, p_cath, walh, b_al, nullptr, nullptr, p_zfh,
        BATCH*ZL, DIM, 2*DIM, 2*DIM, 2*DIM, DIM, 0,0,0, 1,1, 0,0,0, 0,0, 1.f, 0);
    cudaEventRecord(evZf, 0);

    // s2: fusion branch (needs zfh + nsh/nsih + wfush)
    cudaStreamWaitEvent(s2, evZf, 0);
    mm<64,128,__half,__half,float>(s2, p_zfh, p_nsh, nullptr, nullptr, nullptr, p_attnx,
        ZL, SL, DIM, DIM, DIM, SL,
        (long long)ZL*DIM, (long long)SL*DIM, (long long)ZL*SL,
        BATCH, 1, 0,0,0, 0,0, scale_dim, 0);
    mm<64,128,__half,__half,float>(s2, p_zfh, p_nsih, nullptr, nullptr, nullptr, p_attnxi,
        ZL, SL, DIM, DIM, DIM, SL,
        (long long)ZL*DIM, (long long)SL*DIM, (long long)ZL*SL,
        BATCH, 1, 0,0,0, 0,0, scale_dim, 0);
    fusion_kernel<<<BATCH, SL, 0, s2>>>(p_attnx, p_attnxi,
        out + O_ALPHA, out + O_UM, out + O_U, out + O_UI);
    make_v_k<<<cdiv((long long)SLD, 256), 256, 0, s2>>>(p_nsh, p_nsih, out + O_ALPHA, p_vh);
    mm<128,128,__half,__half,float>(s2, p_vh, wfush, b_fus, nullptr, nullptr, p_vf,
        BATCH*SL, DIM, DIM, DIM, DIM, DIM, 0,0,0, 1,1, 0,0,0, 0,0, 1.f, 0);
    cudaEventRecord(evJoin, s2);

    // ======= main chain: MHA (needs wqkvh from s2) =======
    {
        static bool ainit = false;
        if (!ainit) {
            cudaFuncSetAttribute(attn_fused, cudaFuncAttributeMaxDynamicSharedMemorySize, PV_SMEM);
            ainit = true;
        }
    }
    ln_cat_kernel<<<dim3(NN, BATCH, 2), 256>>>(p_zfh, x, xi, p_lnh2, g1, bt1);
    cudaStreamWaitEvent(0, evW, 0);
    mm<128,128,__half,__half,__half>(0, p_lnh2, wqkvh, b_qkv, nullptr, nullptr, p_qkvh2,
        BATCH*NN, QKV3, DIM, DIM, DIM, QKV3,
        (long long)NND, 0, (long long)NNQ, 2, 1, 0,0,0, 0,0, 1.f, 0);
    attn_fused<<<dim3(3, 2*BATCH*HEADS), 512, PV_SMEM>>>(
        p_qkvh2, out + O_ATTN, p_aoh2);
    mm<128,128,__half,__half,float>(0, p_aoh2, wprojh, b_proj, nullptr, nullptr, p_xattn2,
        BATCH*NN, DIM, DIM, DIM, DIM, DIM,
        (long long)NND, 0, (long long)NND, 2, 1, 0,0,0, 0,0, 1.f, 0);

    // ======= JOIN: need p_vf =======
    cudaStreamWaitEvent(0, evJoin, 0);

    // ---- fused residual + 3x LN ----
    resid_ln_k<<<dim3(TT, BATCH), 256>>>(x, xi, p_xattn2, p_vf, g2, bt2,
                                         p_xnew2, p_lnvh, p_lnx2);
    cudaEventRecord(evResid, 0);

    // ---- adap2 on s2, concurrent with fc1 ----
    cudaStreamWaitEvent(s2, evResid, 0);
    mm<128,128,__half,__half,float>(s2, p_lnvh, wal2h, b_al2, nullptr, nullptr, p_adap2,
        BATCH*TT, DIM, DIM, DIM, DIM, DIM, 0,0,0, 1,1, 0,0,0, 0,0, 1.f, 0);
    cudaEventRecord(evAdap, s2);

    // ---- fc1 (main), then fc2 needs adap2 ----
    mm<128,128,__half,__half,__half>(0, p_lnx2, wfc1h, b_fc1, nullptr, nullptr, p_hh2,
        BATCH*TT, HID, DIM, DIM, DIM, HID,
        (long long)TTD, 0, (long long)TTH, 2, 1, 0,0,0, 0,0, 1.f, 1);
    cudaStreamWaitEvent(0, evAdap, 0);
    mm<128,128,__half,__half,float>(0, p_hh2, wfc2h, b_fc2, p_xnew2, p_adap2, out + O_XOUT,
        BATCH*TT, DIM, HID, HID, HID, DIM,
        (long long)TTH, 0, SIDE_OUT, 2, 1, 0,0,0,
        (long long)TTD, 0, 1.f, 0);
}